// round 1
// baseline (speedup 1.0000x reference)
#include <cuda_runtime.h>
#include <cuda_bf16.h>
#include <cstdint>

#define BB 8
#define SS 1024
#define HH 128

// ---------------- scratch (32 MB) ----------------
__device__ float g_scores[(size_t)BB * SS * SS];

// ---------------- Kernel A: scores[b,i,j] = sum_h x[b,j,h]*rel[i,j,h] ----------------
#define TI 16
#define TJ 32
#define HC 32
#define HP 36   // padded h-chunk row (conflict-free for stride-HP float4 reads)

__global__ void scores_kernel(const float* __restrict__ x,
                              const float* __restrict__ rel,
                              float* __restrict__ scores) {
    extern __shared__ float sm[];
    float* rel_s = sm;                         // [TI][TJ][HP]
    float* x_s   = sm + TI * TJ * HP;          // [BB][TJ][HP]

    const int t  = threadIdx.x;                // 256 threads
    const int i0 = blockIdx.y * TI;
    const int j0 = blockIdx.x * TJ;
    const int j  = t & 31;                     // lane = local j
    const int g  = t >> 5;                     // warp id 0..7
    const int tig = g & 3;                     // 4 groups of 4 i-rows
    const int bg  = g >> 2;                    // 2 groups of 4 batches

    float acc[4][4];
#pragma unroll
    for (int p = 0; p < 4; p++)
#pragma unroll
        for (int q = 0; q < 4; q++) acc[p][q] = 0.f;

    for (int hc = 0; hc < HH / HC; hc++) {
        // stage rel tile: TI*TJ rows x 8 float4
        for (int idx = t; idx < TI * TJ * 8; idx += 256) {
            int pair = idx >> 3, f4 = idx & 7;
            int il = pair >> 5, jl = pair & 31;
            float4 v = *(const float4*)(rel + ((size_t)(i0 + il) * SS + (j0 + jl)) * HH + hc * HC + f4 * 4);
            *(float4*)(rel_s + (il * TJ + jl) * HP + f4 * 4) = v;
        }
        // stage x tile: BB*TJ rows x 8 float4
        for (int idx = t; idx < BB * TJ * 8; idx += 256) {
            int pair = idx >> 3, f4 = idx & 7;
            int bl = pair >> 5, jl = pair & 31;
            float4 v = *(const float4*)(x + ((size_t)bl * SS + (j0 + jl)) * HH + hc * HC + f4 * 4);
            *(float4*)(x_s + (bl * TJ + jl) * HP + f4 * 4) = v;
        }
        __syncthreads();

#pragma unroll
        for (int h4 = 0; h4 < HC / 4; h4++) {
            float4 r[4], xv[4];
#pragma unroll
            for (int p = 0; p < 4; p++)
                r[p] = *(float4*)(rel_s + ((tig * 4 + p) * TJ + j) * HP + h4 * 4);
#pragma unroll
            for (int q = 0; q < 4; q++)
                xv[q] = *(float4*)(x_s + ((bg * 4 + q) * TJ + j) * HP + h4 * 4);
#pragma unroll
            for (int p = 0; p < 4; p++)
#pragma unroll
                for (int q = 0; q < 4; q++) {
                    acc[p][q] += r[p].x * xv[q].x;
                    acc[p][q] += r[p].y * xv[q].y;
                    acc[p][q] += r[p].z * xv[q].z;
                    acc[p][q] += r[p].w * xv[q].w;
                }
        }
        __syncthreads();
    }

#pragma unroll
    for (int p = 0; p < 4; p++)
#pragma unroll
        for (int q = 0; q < 4; q++) {
            int i = i0 + tig * 4 + p;
            int b = bg * 4 + q;
            scores[((size_t)b * SS + i) * SS + j0 + j] = acc[p][q];
        }
}

// ---------------- Kernel S: softmax over j, in place ----------------
__global__ void softmax_kernel(float* __restrict__ scores) {
    __shared__ float red[8];
    const int row = blockIdx.x;                 // b*S + i
    float* p = scores + (size_t)row * SS;
    const int t = threadIdx.x;                  // 256 threads, 4 elems each

    float4 v = *(float4*)(p + t * 4);
    float m = fmaxf(fmaxf(v.x, v.y), fmaxf(v.z, v.w));
#pragma unroll
    for (int o = 16; o > 0; o >>= 1) m = fmaxf(m, __shfl_xor_sync(0xffffffffu, m, o));
    if ((t & 31) == 0) red[t >> 5] = m;
    __syncthreads();
    float M = red[0];
#pragma unroll
    for (int k = 1; k < 8; k++) M = fmaxf(M, red[k]);

    v.x = __expf(v.x - M);
    v.y = __expf(v.y - M);
    v.z = __expf(v.z - M);
    v.w = __expf(v.w - M);
    float s = v.x + v.y + v.z + v.w;
#pragma unroll
    for (int o = 16; o > 0; o >>= 1) s += __shfl_xor_sync(0xffffffffu, s, o);
    __syncthreads();                            // protect red before rewrite
    if ((t & 31) == 0) red[t >> 5] = s;
    __syncthreads();
    float tot = 0.f;
#pragma unroll
    for (int k = 0; k < 8; k++) tot += red[k];
    float inv = 1.0f / tot;
    v.x *= inv; v.y *= inv; v.z *= inv; v.w *= inv;
    *(float4*)(p + t * 4) = v;
}

// ---------------- Kernel B: out[b,i,h] = sum_j w[b,i,j]*x[b,j,h] ----------------
#define MT 64
#define KT 32

__global__ void out_kernel(const float* __restrict__ w,
                           const float* __restrict__ x,
                           float* __restrict__ out) {
    __shared__ float w_s[MT][KT + 4];           // 64 x 36
    __shared__ float x_s[KT][HH + 4];           // 32 x 132

    const int t  = threadIdx.x;                 // 256 threads
    const int b  = blockIdx.y;
    const int m0 = blockIdx.x * MT;
    const int tx = t & 31;                      // h quad index (32 x 4 = 128)
    const int ty = t >> 5;                      // m group (8 groups x 8 rows)

    const float* wb = w + (size_t)b * SS * SS;
    const float* xb = x + (size_t)b * SS * HH;

    float acc[8][4];
#pragma unroll
    for (int p = 0; p < 8; p++)
#pragma unroll
        for (int q = 0; q < 4; q++) acc[p][q] = 0.f;

    for (int k0 = 0; k0 < SS; k0 += KT) {
        // stage w tile: 64 rows x 8 float4
        for (int idx = t; idx < MT * (KT / 4); idx += 256) {
            int row = idx >> 3, f4 = idx & 7;
            *(float4*)&w_s[row][f4 * 4] =
                *(const float4*)(wb + (size_t)(m0 + row) * SS + k0 + f4 * 4);
        }
        // stage x tile: 32 rows x 32 float4
        for (int idx = t; idx < KT * (HH / 4); idx += 256) {
            int row = idx >> 5, f4 = idx & 31;
            *(float4*)&x_s[row][f4 * 4] =
                *(const float4*)(xb + (size_t)(k0 + row) * HH + f4 * 4);
        }
        __syncthreads();

#pragma unroll
        for (int k4 = 0; k4 < KT / 4; k4++) {
            float4 af[8];
#pragma unroll
            for (int p = 0; p < 8; p++)
                af[p] = *(float4*)&w_s[ty * 8 + p][k4 * 4];
            float4 bf[4];
#pragma unroll
            for (int kk = 0; kk < 4; kk++)
                bf[kk] = *(float4*)&x_s[k4 * 4 + kk][tx * 4];
#pragma unroll
            for (int p = 0; p < 8; p++) {
                acc[p][0] += af[p].x * bf[0].x; acc[p][0] += af[p].y * bf[1].x;
                acc[p][0] += af[p].z * bf[2].x; acc[p][0] += af[p].w * bf[3].x;
                acc[p][1] += af[p].x * bf[0].y; acc[p][1] += af[p].y * bf[1].y;
                acc[p][1] += af[p].z * bf[2].y; acc[p][1] += af[p].w * bf[3].y;
                acc[p][2] += af[p].x * bf[0].z; acc[p][2] += af[p].y * bf[1].z;
                acc[p][2] += af[p].z * bf[2].z; acc[p][2] += af[p].w * bf[3].z;
                acc[p][3] += af[p].x * bf[0].w; acc[p][3] += af[p].y * bf[1].w;
                acc[p][3] += af[p].z * bf[2].w; acc[p][3] += af[p].w * bf[3].w;
            }
        }
        __syncthreads();
    }

#pragma unroll
    for (int p = 0; p < 8; p++) {
        float4 o = make_float4(acc[p][0], acc[p][1], acc[p][2], acc[p][3]);
        *(float4*)(out + ((size_t)b * SS + m0 + ty * 8 + p) * HH + tx * 4) = o;
    }
}

// ---------------- launch ----------------
extern "C" void kernel_launch(void* const* d_in, const int* in_sizes, int n_in,
                              void* d_out, int out_size) {
    const float* x   = (const float*)d_in[0];   // (8, 1024, 128) f32
    const float* rel = (const float*)d_in[1];   // (1024, 1024, 128) f32
    float* out = (float*)d_out;                 // (8, 1024, 128) f32

    float* scores = nullptr;
    cudaGetSymbolAddress((void**)&scores, g_scores);

    const int smemA = (TI * TJ * HP + BB * TJ * HP) * sizeof(float);  // 110,592 B
    cudaFuncSetAttribute(scores_kernel, cudaFuncAttributeMaxDynamicSharedMemorySize, smemA);

    dim3 gridA(SS / TJ, SS / TI);   // (32, 64)
    scores_kernel<<<gridA, 256, smemA>>>(x, rel, scores);

    softmax_kernel<<<BB * SS, 256>>>(scores);

    dim3 gridB(SS / MT, BB);        // (16, 8)
    out_kernel<<<gridB, 256>>>(scores, x, out);
}

// round 2
// speedup vs baseline: 1.5210x; 1.5210x over previous
#include <cuda_runtime.h>
#include <cstdint>

#define BB 8
#define SS 1024
#define HH 128

// ---------------- scratch (32 MB) ----------------
__device__ float g_scores[(size_t)BB * SS * SS];

// ---------------- helpers: f32x2 packed math + cp.async ----------------
__device__ __forceinline__ void ffma2(unsigned long long &acc, unsigned long long a, unsigned long long b) {
    asm("fma.rn.f32x2 %0, %1, %2, %0;" : "+l"(acc) : "l"(a), "l"(b));
}
__device__ __forceinline__ unsigned long long pack2(float v) {
    unsigned long long r;
    asm("mov.b64 %0, {%1, %1};" : "=l"(r) : "f"(v));
    return r;
}
__device__ __forceinline__ void unpack2(unsigned long long p, float &lo, float &hi) {
    asm("mov.b64 {%0, %1}, %2;" : "=f"(lo), "=f"(hi) : "l"(p));
}
__device__ __forceinline__ void cpa16(uint32_t s, const void* g) {
    asm volatile("cp.async.cg.shared.global [%0], [%1], 16;" :: "r"(s), "l"(g));
}
#define CP_COMMIT() asm volatile("cp.async.commit_group;" ::: "memory")
#define CP_WAIT1()  asm volatile("cp.async.wait_group 1;" ::: "memory")

// =====================================================================
// Kernel A: scores[b,i,j] = sum_h x[b,j,h]*rel[i,j,h]
// Block: 256 thr = 32 j lanes x (4 i-groups x 2 b-groups).
// Thread tile: 8 i x 4 b, all h. rel single-use/thread, x in regs per h4.
// Triple-buffered cp.async pipeline, HC=8 h per chunk.
// =====================================================================
#define TIA 32
#define TJA 32
#define HCA 8
#define NCHA (HH / HCA)          // 16 chunks
#define RF4 3                    // 2 data float4 + 1 pad per (i,j) row
#define RELF4 (TIA * TJA * RF4)  // 3072 float4 = 48KB
#define XF4   (BB * TJA * RF4)   // 768 float4  = 12KB
#define BUFF4 (RELF4 + XF4)      // 3840 float4 = 60KB
#define NBUFA 3                  // 180KB dynamic smem

__global__ void __launch_bounds__(256, 1)
scores_kernel(const float* __restrict__ x,
              const float* __restrict__ rel,
              float* __restrict__ scores) {
    extern __shared__ float4 smA[];
    const int t   = threadIdx.x;
    const int j   = t & 31;
    const int g   = t >> 5;
    const int tig = g & 3;       // i-group: rows tig*8 .. +7
    const int bg  = g >> 1 >> 1; // b-group: 0 or 1 (4 b each)
    const int i0  = blockIdx.y * TIA;
    const int j0  = blockIdx.x * TJA;
    const uint32_t sbase = (uint32_t)__cvta_generic_to_shared(smA);

    auto stage = [&](int c, int s) {
        uint32_t b4 = sbase + (uint32_t)s * (BUFF4 * 16);
        // rel chunk: 32i x 32j x 2 float4 = 2048 f4 -> 8 per thread (coalesced pairs)
#pragma unroll
        for (int k = 0; k < 8; k++) {
            int idx = t + k * 256;
            int f = idx & 1, jj = (idx >> 1) & 31, ii = idx >> 6;
            const float* gp = rel + ((size_t)(i0 + ii) * SS + (j0 + jj)) * HH + c * HCA + f * 4;
            cpa16(b4 + (uint32_t)((ii * TJA + jj) * RF4 + f) * 16, gp);
        }
        // x chunk: 8b x 32j x 2 float4 = 512 f4 -> 2 per thread
#pragma unroll
        for (int k = 0; k < 2; k++) {
            int idx = t + k * 256;
            int f = idx & 1, jj = (idx >> 1) & 31, bb = idx >> 6;
            const float* gp = x + ((size_t)bb * SS + (j0 + jj)) * HH + c * HCA + f * 4;
            cpa16(b4 + (uint32_t)(RELF4 + (bb * TJA + jj) * RF4 + f) * 16, gp);
        }
    };

    stage(0, 0); CP_COMMIT();
    stage(1, 1); CP_COMMIT();

    unsigned long long acc[8][4] = {};   // (even-h, odd-h) partial pairs

    int buf = 0;
    for (int c = 0; c < NCHA; c++) {
        CP_WAIT1();
        __syncthreads();
        if (c + 2 < NCHA) {
            int nb = buf + 2; if (nb >= NBUFA) nb -= NBUFA;
            stage(c + 2, nb);
        }
        CP_COMMIT();

        const float4* rb = smA + (size_t)buf * BUFF4 + ((tig * 8) * TJA + j) * RF4;
        const float4* xb = smA + (size_t)buf * BUFF4 + RELF4 + ((bg * 4) * TJA + j) * RF4;
#pragma unroll
        for (int f = 0; f < 2; f++) {
            ulonglong2 xv[4];
#pragma unroll
            for (int q = 0; q < 4; q++)
                xv[q] = *reinterpret_cast<const ulonglong2*>(xb + q * (TJA * RF4) + f);
#pragma unroll
            for (int p = 0; p < 8; p++) {
                ulonglong2 rv = *reinterpret_cast<const ulonglong2*>(rb + p * (TJA * RF4) + f);
#pragma unroll
                for (int q = 0; q < 4; q++) {
                    ffma2(acc[p][q], rv.x, xv[q].x);
                    ffma2(acc[p][q], rv.y, xv[q].y);
                }
            }
        }
        buf++; if (buf == NBUFA) buf = 0;
    }

#pragma unroll
    for (int p = 0; p < 8; p++)
#pragma unroll
        for (int q = 0; q < 4; q++) {
            float lo, hi; unpack2(acc[p][q], lo, hi);
            scores[((size_t)(bg * 4 + q) * SS + (i0 + tig * 8 + p)) * SS + j0 + j] = lo + hi;
        }
}

// ---------------- Kernel S: softmax over j, in place ----------------
__global__ void softmax_kernel(float* __restrict__ scores) {
    __shared__ float red[8];
    const int row = blockIdx.x;
    float* p = scores + (size_t)row * SS;
    const int t = threadIdx.x;

    float4 v = *(float4*)(p + t * 4);
    float m = fmaxf(fmaxf(v.x, v.y), fmaxf(v.z, v.w));
#pragma unroll
    for (int o = 16; o > 0; o >>= 1) m = fmaxf(m, __shfl_xor_sync(0xffffffffu, m, o));
    if ((t & 31) == 0) red[t >> 5] = m;
    __syncthreads();
    float M = red[0];
#pragma unroll
    for (int k = 1; k < 8; k++) M = fmaxf(M, red[k]);

    v.x = __expf(v.x - M); v.y = __expf(v.y - M);
    v.z = __expf(v.z - M); v.w = __expf(v.w - M);
    float s = v.x + v.y + v.z + v.w;
#pragma unroll
    for (int o = 16; o > 0; o >>= 1) s += __shfl_xor_sync(0xffffffffu, s, o);
    __syncthreads();
    if ((t & 31) == 0) red[t >> 5] = s;
    __syncthreads();
    float tot = 0.f;
#pragma unroll
    for (int k = 0; k < 8; k++) tot += red[k];
    float inv = 1.0f / tot;
    v.x *= inv; v.y *= inv; v.z *= inv; v.w *= inv;
    *(float4*)(p + t * 4) = v;
}

// =====================================================================
// Kernel B: out[b,i,h] = sum_j w[b,i,j]*x[b,j,h]
// 128 thr: tx(32)=h quad, ty(4)=i-group of 8. Block 32i x 128h per b.
// f32x2 packed over (h,h+1): w broadcast pair (1 mov), x pairs natural.
// Triple-buffered cp.async, KT=32 j per chunk.
// =====================================================================
#define MTB 32
#define KTB 32
#define NCHB (SS / KTB)      // 32 chunks
#define WROW 36
#define XROW 132
#define WF (MTB * WROW)      // 1152 floats
#define XFB (KTB * XROW)     // 4224 floats
#define BUFBF (WF + XFB)     // 5376 floats = 21504 B
#define NBUFB 3              // 64512 B dynamic smem

__global__ void __launch_bounds__(128, 1)
out_kernel(const float* __restrict__ w,
           const float* __restrict__ x,
           float* __restrict__ out) {
    extern __shared__ float smB[];
    const int t  = threadIdx.x;
    const int tx = t & 31;       // h quad
    const int ty = t >> 5;       // 0..3
    const int b  = blockIdx.y;
    const int m0 = blockIdx.x * MTB;
    const float* wb = w + (size_t)b * SS * SS;
    const float* xb = x + (size_t)b * SS * HH;
    const uint32_t sbase = (uint32_t)__cvta_generic_to_shared(smB);

    auto stage = [&](int c, int s) {
        uint32_t bbase = sbase + (uint32_t)s * (BUFBF * 4);
        // w: 32 rows x 8 float4 = 256 f4 -> 2 per thread
#pragma unroll
        for (int k = 0; k < 2; k++) {
            int idx = t + k * 128;
            int f4 = idx & 7, row = idx >> 3;
            cpa16(bbase + (uint32_t)(row * WROW + f4 * 4) * 4,
                  wb + (size_t)(m0 + row) * SS + c * KTB + f4 * 4);
        }
        // x: 32 rows x 32 float4 = 1024 f4 -> 8 per thread
#pragma unroll
        for (int k = 0; k < 8; k++) {
            int idx = t + k * 128;
            int f4 = idx & 31, row = idx >> 5;
            cpa16(bbase + (uint32_t)(WF + row * XROW + f4 * 4) * 4,
                  xb + (size_t)(c * KTB + row) * HH + f4 * 4);
        }
    };

    stage(0, 0); CP_COMMIT();
    stage(1, 1); CP_COMMIT();

    unsigned long long acc[8][2] = {};   // 8 i x (2 h-pairs = 4 h)

    int buf = 0;
    for (int c = 0; c < NCHB; c++) {
        CP_WAIT1();
        __syncthreads();
        if (c + 2 < NCHB) {
            int nb = buf + 2; if (nb >= NBUFB) nb -= NBUFB;
            stage(c + 2, nb);
        }
        CP_COMMIT();

        const float* wsb = smB + (size_t)buf * BUFBF;
        const float* xsb = wsb + WF;
#pragma unroll
        for (int j4 = 0; j4 < KTB / 4; j4++) {
            float4 wv[8];
#pragma unroll
            for (int p = 0; p < 8; p++)
                wv[p] = *reinterpret_cast<const float4*>(wsb + (ty * 8 + p) * WROW + j4 * 4);
#pragma unroll
            for (int jj = 0; jj < 4; jj++) {
                ulonglong2 xv = *reinterpret_cast<const ulonglong2*>(xsb + (j4 * 4 + jj) * XROW + tx * 4);
#pragma unroll
                for (int p = 0; p < 8; p++) {
                    float wval = (jj == 0) ? wv[p].x : (jj == 1) ? wv[p].y : (jj == 2) ? wv[p].z : wv[p].w;
                    unsigned long long wp = pack2(wval);
                    ffma2(acc[p][0], wp, xv.x);
                    ffma2(acc[p][1], wp, xv.y);
                }
            }
        }
        buf++; if (buf == NBUFB) buf = 0;
    }

#pragma unroll
    for (int p = 0; p < 8; p++) {
        float4 o;
        unpack2(acc[p][0], o.x, o.y);
        unpack2(acc[p][1], o.z, o.w);
        *reinterpret_cast<float4*>(out + ((size_t)b * SS + m0 + ty * 8 + p) * HH + tx * 4) = o;
    }
}

// ---------------- launch ----------------
extern "C" void kernel_launch(void* const* d_in, const int* in_sizes, int n_in,
                              void* d_out, int out_size) {
    const float* x   = (const float*)d_in[0];   // (8, 1024, 128) f32
    const float* rel = (const float*)d_in[1];   // (1024, 1024, 128) f32
    float* out = (float*)d_out;                 // (8, 1024, 128) f32

    float* scores = nullptr;
    cudaGetSymbolAddress((void**)&scores, g_scores);

    const int smA_bytes = NBUFA * BUFF4 * 16;   // 184320
    cudaFuncSetAttribute(scores_kernel, cudaFuncAttributeMaxDynamicSharedMemorySize, smA_bytes);
    scores_kernel<<<dim3(SS / TJA, SS / TIA), 256, smA_bytes>>>(x, rel, scores);

    softmax_kernel<<<BB * SS, 256>>>(scores);

    const int smB_bytes = NBUFB * BUFBF * 4;    // 64512
    cudaFuncSetAttribute(out_kernel, cudaFuncAttributeMaxDynamicSharedMemorySize, smB_bytes);
    out_kernel<<<dim3(SS / MTB, BB), 128, smB_bytes>>>(scores, x, out);
}